// round 16
// baseline (speedup 1.0000x reference)
#include <cuda_runtime.h>
#include <cuda_fp16.h>

#define N_NODES 50000
#define N_EDGES 600000
#define D 128

#define NB 444                       // persistent blocks = 148 SMs * 3 (co-resident)
#define NC 192                       // CSR-builder blocks (first wave guaranteed)
#define CT 2                         // nodes per CSR-thread in scan phases (192*256*2 >= 50000)
#define TILE_R 64                    // GEMM rows per tile
#define GEMM_TILES ((N_NODES + TILE_R - 1) / TILE_R)   // 782

// ---- scratch (device globals: no allocation allowed) ----
__device__ int    g_deg[N_NODES];
__device__ int    g_off[N_NODES + 1];
__device__ int    g_cur[N_NODES];
__device__ float  g_inv[N_NODES];
__device__ int2   g_csr[N_EDGES];             // {src byte-offset, bits(inv[src])}
__device__ __half g_yh[(size_t)N_NODES * D];  // y = x @ W, fp16 (12.8 MB: L2-resident)
__device__ int    g_part[NC];
__device__ int    g_pscan[NC];
__device__ int    g_bar[8];                   // monotonic per launch; reset by k_agg
__device__ int    g_tile;                     // GEMM work-steal cursor; reset by k_agg

__device__ __forceinline__ int load_idx(const void* p, int e, int is64) {
    if (is64) return (int)((const long long*)p)[e];
    return ((const int*)p)[e];
}

// Device barrier among the NC CSR blocks only (monotonic counters; reset by the
// trailing k_agg launch, which is stream-ordered after k_main -> no reset race).
__device__ __forceinline__ void barwait(int id, int target) {
    __syncthreads();
    if (threadIdx.x == 0) {
        __threadfence();                       // release my writes
        atomicAdd(&g_bar[id], 1);
        while (atomicAdd(&g_bar[id], 0) < target) __nanosleep(32);
    }
    __syncthreads();
    __threadfence();                           // acquire others' writes
}

// ---- packed f32x2 helpers (FFMA2 reachable only via PTX) ----
__device__ __forceinline__ unsigned long long pk2(float lo, float hi) {
    unsigned long long r;
    asm("mov.b64 %0, {%1, %2};" : "=l"(r) : "f"(lo), "f"(hi));
    return r;
}
__device__ __forceinline__ unsigned long long ffma2(unsigned long long a,
                                                    unsigned long long b,
                                                    unsigned long long c) {
    unsigned long long d;
    asm("fma.rn.f32x2 %0, %1, %2, %3;" : "=l"(d) : "l"(a), "l"(b), "l"(c));
    return d;
}
__device__ __forceinline__ float2 unpk2(unsigned long long v) {
    float2 f;
    asm("mov.b64 {%0, %1}, %2;" : "=f"(f.x), "=f"(f.y) : "l"(v));
    return f;
}

// ---- GEMM tile: y[row0..row0+63] = x[row0..row0+63] @ W, stored as fp16.
// A staged TRANSPOSED in smem (As[k][r]) so each thread's 8 row-values for a
// given k are contiguous -> 2x LDS.128 yields row-PAIR-packed u64 operands for
// FFMA2 with no packing MOVs. As is __align__(16) so the 128-bit LDS is legal.
// W stays in its native 64 KB layout (L1-hot); the duplicated-w operand is
// built with pk2 MOVs in-loop (a 128 KB pre-dup W blows L1 and regresses, R13).
__device__ __forceinline__ void gemm_body(int blk, const float* __restrict__ x,
                                          const float* __restrict__ W) {
    __shared__ __align__(16) float As[D * TILE_R];   // As[k*64 + r], 32 KB
    int row0 = blk * TILE_R;
    int t = threadIdx.x;

    // stage x tile transposed: 64 rows x 32 float4-cols, 2048 float4s / 256 thr
    for (int i = t; i < TILE_R * (D / 4); i += 256) {
        int r  = i & (TILE_R - 1);
        int c4 = i >> 6;
        int row = row0 + r;
        float4 v = (row < N_NODES)
                       ? ((const float4*)(x + (size_t)row * D))[c4]
                       : make_float4(0.f, 0.f, 0.f, 0.f);
        As[(c4 * 4 + 0) * TILE_R + r] = v.x;
        As[(c4 * 4 + 1) * TILE_R + r] = v.y;
        As[(c4 * 4 + 2) * TILE_R + r] = v.z;
        As[(c4 * 4 + 3) * TILE_R + r] = v.w;
    }
    __syncthreads();

    int tc = t & 31;   // col group: cols 4*tc .. 4*tc+3
    int tr = t >> 5;   // row group: rows 8*tr .. 8*tr+7

    unsigned long long acc[4][4];              // [rowpair][col]
    #pragma unroll
    for (int rp = 0; rp < 4; rp++)
        #pragma unroll
        for (int c = 0; c < 4; c++) acc[rp][c] = 0ULL;

    const float* as_base = As + tr * 8;        // (k*64 + tr*8)*4B: 32B-multiple offsets

    #pragma unroll 4
    for (int k = 0; k < D; k++) {
        float4 w = ((const float4*)(W + (size_t)k * D))[tc];
        unsigned long long w2[4];
        w2[0] = pk2(w.x, w.x);
        w2[1] = pk2(w.y, w.y);
        w2[2] = pk2(w.z, w.z);
        w2[3] = pk2(w.w, w.w);
        ulonglong2 A0 = *(const ulonglong2*)(as_base + k * TILE_R);      // rows 0-3
        ulonglong2 A1 = *(const ulonglong2*)(as_base + k * TILE_R + 4);  // rows 4-7
        #pragma unroll
        for (int c = 0; c < 4; c++) {
            acc[0][c] = ffma2(A0.x, w2[c], acc[0][c]);
            acc[1][c] = ffma2(A0.y, w2[c], acc[1][c]);
            acc[2][c] = ffma2(A1.x, w2[c], acc[2][c]);
            acc[3][c] = ffma2(A1.y, w2[c], acc[3][c]);
        }
    }

    #pragma unroll
    for (int rp = 0; rp < 4; rp++) {
        float2 c0 = unpk2(acc[rp][0]);
        float2 c1 = unpk2(acc[rp][1]);
        float2 c2 = unpk2(acc[rp][2]);
        float2 c3 = unpk2(acc[rp][3]);
        int r_lo = row0 + tr * 8 + rp * 2;
        int r_hi = r_lo + 1;
        if (r_lo < N_NODES) {
            __half2 p0 = __floats2half2_rn(c0.x, c1.x);
            __half2 p1 = __floats2half2_rn(c2.x, c3.x);
            uint2 u;
            u.x = *(unsigned int*)&p0;
            u.y = *(unsigned int*)&p1;
            ((uint2*)(g_yh + (size_t)r_lo * D))[tc] = u;
        }
        if (r_hi < N_NODES) {
            __half2 p0 = __floats2half2_rn(c0.y, c1.y);
            __half2 p1 = __floats2half2_rn(c2.y, c3.y);
            uint2 u;
            u.x = *(unsigned int*)&p0;
            u.y = *(unsigned int*)&p1;
            ((uint2*)(g_yh + (size_t)r_hi * D))[tc] = u;
        }
    }
    __syncthreads();   // protect As before next tile
}

// Work-stealing GEMM loop: grab tiles from the global cursor until drained.
__device__ __forceinline__ void gemm_steal(const float* __restrict__ x,
                                           const float* __restrict__ W) {
    __shared__ int s_tile;
    for (;;) {
        __syncthreads();                       // protect s_tile reuse
        if (threadIdx.x == 0) s_tile = atomicAdd(&g_tile, 1);
        __syncthreads();
        int tile = s_tile;
        if (tile >= GEMM_TILES) break;
        gemm_body(tile, x, W);
    }
}

// ---- Launch 1: persistent kernel (zero + build + GEMM, work-conserving).
// Blocks [0,NC): zero -> count -> scan -> fill (group barriers 0..4), then JOIN
// the GEMM stealing loop. Blocks [NC,NB): GEMM stealing from the start.
// The kernel boundary is the global join before aggregation.
__global__ void __launch_bounds__(256, 3)
k_main(const float* __restrict__ x, const void* __restrict__ src,
       const void* __restrict__ dst, const float* __restrict__ W) {
    int blk = blockIdx.x;
    int t = threadIdx.x;

    if (blk < NC) {
        __shared__ int s_scan[256];
        __shared__ int s_ok;

        // int64/int32 detection, block-local. (JAX without x64 downcasts
        // int64->int32; the odd 32-bit words of src are all zero iff the data
        // is 8-byte little-endian values < 2^31.)
        if (t == 0) s_ok = 1;
        __syncthreads();
        if (t < 64 && ((const unsigned int*)src)[2 * t + 1] != 0u) s_ok = 0;
        // Phase C0: zero the degree array (interleaved with detection)
        for (int i = blk * 256 + t; i < N_NODES; i += NC * 256) g_deg[i] = 0;
        __syncthreads();
        int is64 = s_ok;
        barwait(0, NC);

        // Phase C1: degree histogram
        for (int e = blk * 256 + t; e < N_EDGES; e += NC * 256) {
            int d = load_idx(dst, e, is64);
            atomicAdd(&g_deg[d], 1);
        }
        barwait(1, NC);

        // Phase C2: per-thread partial sums (contiguous CT nodes each)
        int base = (blk * 256 + t) * CT;
        int dcache[CT];
        int mysum = 0;
        #pragma unroll
        for (int i = 0; i < CT; i++) {
            int idx = base + i;
            dcache[i] = (idx < N_NODES) ? g_deg[idx] : 0;
            mysum += dcache[i];
        }
        s_scan[t] = mysum;
        __syncthreads();
        #pragma unroll
        for (int ofs = 1; ofs < 256; ofs <<= 1) {
            int v = (t >= ofs) ? s_scan[t - ofs] : 0;
            __syncthreads();
            s_scan[t] += v;
            __syncthreads();
        }
        int excl = s_scan[t] - mysum;
        if (t == 255) g_part[blk] = s_scan[255];
        barwait(2, NC);

        // Phase C3: warp-scan of the NC block partials (block 0, warp 0)
        if (blk == 0 && t < 32) {
            int carry = 0;
            #pragma unroll
            for (int seg = 0; seg < NC / 32; seg++) {
                int orig = g_part[seg * 32 + t];
                int v = orig;
                #pragma unroll
                for (int o = 1; o < 32; o <<= 1) {
                    int u = __shfl_up_sync(0xFFFFFFFFu, v, o);
                    if (t >= o) v += u;
                }
                g_pscan[seg * 32 + t] = carry + v - orig;   // exclusive
                carry += __shfl_sync(0xFFFFFFFFu, v, 31);
            }
        }
        barwait(3, NC);

        // Phase C4: write offsets, cursors, rsqrt(deg)
        int run = g_pscan[blk] + excl;
        #pragma unroll
        for (int i = 0; i < CT; i++) {
            int idx = base + i;
            if (idx < N_NODES) {
                g_off[idx] = run;
                g_cur[idx] = run;
                g_inv[idx] = rsqrtf((float)dcache[i]);
                run += dcache[i];
                if (idx == N_NODES - 1) g_off[N_NODES] = run;
            }
        }
        barwait(4, NC);

        // Phase C5: CSR fill via atomic cursors. Fuse the source coefficient
        // into the entry ({byte offset, inv[s]}) so the aggregate kernel does
        // one contiguous LDG.64 instead of an index load + dependent gather.
        // The inv[s] gather cost lands HERE, hidden under the concurrent GEMM.
        for (int e = blk * 256 + t; e < N_EDGES; e += NC * 256) {
            int d = load_idx(dst, e, is64);
            int s = load_idx(src, e, is64);
            int pos = atomicAdd(&g_cur[d], 1);
            int2 ent;
            ent.x = s * (D * 2);               // byte offset into g_yh
            ent.y = __float_as_int(g_inv[s]);
            g_csr[pos] = ent;
        }
        // done building -> help finish the GEMM
        gemm_steal(x, W);
    } else {
        // ===== GEMM: y = x @ W (independent of the graph) =====
        gemm_steal(x, W);
    }
}

// ---- Launch 2: gather-aggregate + epilogue (fp16 y gather, fp32 accumulate).
// One warp per node; each lane owns 4 cols (8B load per neighbor row).
// Unroll-8 head (avg degree ~12 -> most edges covered by one 8-deep burst,
// MLP 8), then unroll-4, then scalar tail. Entry loads stay narrow (LDG.64)
// and independent — int4 pairing halves entry MLP and regresses (R14).
// out[d] = inv[d] * sum_{s in N(d)} inv[s] * y[s]  +  deg[d] * b
// Also resets the barrier/tile counters for the next replay (stream-ordered
// after k_main, so no race with the polls).
__global__ void __launch_bounds__(256)
k_agg(const float* __restrict__ b, float* __restrict__ out) {
    if (blockIdx.x == 0) {
        if (threadIdx.x < 8) g_bar[threadIdx.x] = 0;
        if (threadIdx.x == 8) g_tile = 0;
    }

    int w    = (blockIdx.x * blockDim.x + threadIdx.x) >> 5;
    int lane = threadIdx.x & 31;
    if (w >= N_NODES) return;
    int beg = g_off[w];
    int end = g_off[w + 1];

    const char* ybase = (const char*)g_yh + lane * 8;   // lane's 8B column slice
    float4 acc = make_float4(0.f, 0.f, 0.f, 0.f);
    int e = beg;

    // unroll-8 burst: 8 entry loads then 8 independent y loads (MLP>=8)
    for (; e + 8 <= end; e += 8) {
        int2 p[8];
        #pragma unroll
        for (int j = 0; j < 8; j++) p[j] = g_csr[e + j];
        uint2 u[8];
        #pragma unroll
        for (int j = 0; j < 8; j++) u[j] = *(const uint2*)(ybase + p[j].x);
        #pragma unroll
        for (int j = 0; j < 8; j++) {
            float c = __int_as_float(p[j].y);
            float2 a = __half22float2(*(__half2*)&u[j].x);
            float2 bb = __half22float2(*(__half2*)&u[j].y);
            acc.x += c * a.x;
            acc.y += c * a.y;
            acc.z += c * bb.x;
            acc.w += c * bb.y;
        }
    }
    // unroll-4
    for (; e + 4 <= end; e += 4) {
        int2 p0 = g_csr[e];
        int2 p1 = g_csr[e + 1];
        int2 p2 = g_csr[e + 2];
        int2 p3 = g_csr[e + 3];
        float c0 = __int_as_float(p0.y);
        float c1 = __int_as_float(p1.y);
        float c2 = __int_as_float(p2.y);
        float c3 = __int_as_float(p3.y);
        uint2 u0 = *(const uint2*)(ybase + p0.x);
        uint2 u1 = *(const uint2*)(ybase + p1.x);
        uint2 u2 = *(const uint2*)(ybase + p2.x);
        uint2 u3 = *(const uint2*)(ybase + p3.x);
        float2 a0 = __half22float2(*(__half2*)&u0.x), b0 = __half22float2(*(__half2*)&u0.y);
        float2 a1 = __half22float2(*(__half2*)&u1.x), b1 = __half22float2(*(__half2*)&u1.y);
        float2 a2 = __half22float2(*(__half2*)&u2.x), b2 = __half22float2(*(__half2*)&u2.y);
        float2 a3 = __half22float2(*(__half2*)&u3.x), b3 = __half22float2(*(__half2*)&u3.y);
        acc.x += c0 * a0.x + c1 * a1.x + c2 * a2.x + c3 * a3.x;
        acc.y += c0 * a0.y + c1 * a1.y + c2 * a2.y + c3 * a3.y;
        acc.z += c0 * b0.x + c1 * b1.x + c2 * b2.x + c3 * b3.x;
        acc.w += c0 * b0.y + c1 * b1.y + c2 * b2.y + c3 * b3.y;
    }
    for (; e < end; e++) {
        int2 p = g_csr[e];
        float c = __int_as_float(p.y);
        uint2 u = *(const uint2*)(ybase + p.x);
        float2 a = __half22float2(*(__half2*)&u.x);
        float2 bb = __half22float2(*(__half2*)&u.y);
        acc.x += c * a.x; acc.y += c * a.y; acc.z += c * bb.x; acc.w += c * bb.y;
    }

    float invd = g_inv[w];
    float degf = (float)g_deg[w];
    float4 bv = ((const float4*)b)[lane];
    float4 o;
    o.x = invd * acc.x + degf * bv.x;
    o.y = invd * acc.y + degf * bv.y;
    o.z = invd * acc.z + degf * bv.z;
    o.w = invd * acc.w + degf * bv.w;
    ((float4*)(out + (size_t)w * D))[lane] = o;
}

extern "C" void kernel_launch(void* const* d_in, const int* in_sizes, int n_in,
                              void* d_out, int out_size) {
    const float* x   = (const float*)d_in[0];
    const void*  src = d_in[1];
    const void*  dst = d_in[2];
    const float* W   = (const float*)d_in[3];
    const float* b   = (const float*)d_in[4];
    float* out = (float*)d_out;

    (void)in_sizes; (void)n_in; (void)out_size;

    k_main<<<NB, 256>>>(x, src, dst, W);
    k_agg<<<(N_NODES * 32 + 255) / 256, 256>>>(b, out);
}

// round 17
// speedup vs baseline: 1.0933x; 1.0933x over previous
#include <cuda_runtime.h>
#include <cuda_fp16.h>

#define N_NODES 50000
#define N_EDGES 600000
#define D 128

#define NB 444                       // persistent blocks = 148 SMs * 3 (co-resident)
#define NC 128                       // CSR-builder blocks (first wave guaranteed)
#define CT 2                         // nodes per CSR-thread in scan phases (128*256*2 >= 50000)
#define TILE_R 64                    // GEMM rows per tile
#define GEMM_TILES ((N_NODES + TILE_R - 1) / TILE_R)   // 782

// ---- scratch (device globals: no allocation allowed) ----
__device__ int    g_deg[N_NODES];
__device__ int    g_off[N_NODES + 1];
__device__ int    g_cur[N_NODES];
__device__ float  g_inv[N_NODES];
__device__ int2   g_csr[N_EDGES];             // {src byte-offset, bits(inv[src])}
__device__ __half g_yh[(size_t)N_NODES * D];  // y = x @ W, fp16 (12.8 MB: L2-resident)
__device__ int    g_part[NC];
__device__ int    g_pscan[NC];
__device__ int    g_bar[8];                   // monotonic per launch; reset by k_agg
__device__ int    g_tile;                     // GEMM work-steal cursor; reset by k_agg

__device__ __forceinline__ int load_idx(const void* p, int e, int is64) {
    if (is64) return (int)((const long long*)p)[e];
    return ((const int*)p)[e];
}

// Device barrier among the NC CSR blocks only (monotonic counters; reset by the
// trailing k_agg launch, which is stream-ordered after k_main -> no reset race).
__device__ __forceinline__ void barwait(int id, int target) {
    __syncthreads();
    if (threadIdx.x == 0) {
        __threadfence();                       // release my writes
        atomicAdd(&g_bar[id], 1);
        while (atomicAdd(&g_bar[id], 0) < target) __nanosleep(32);
    }
    __syncthreads();
    __threadfence();                           // acquire others' writes
}

// ---- packed f32x2 helpers (FFMA2 reachable only via PTX) ----
__device__ __forceinline__ unsigned long long pk2(float lo, float hi) {
    unsigned long long r;
    asm("mov.b64 %0, {%1, %2};" : "=l"(r) : "f"(lo), "f"(hi));
    return r;
}
__device__ __forceinline__ unsigned long long ffma2(unsigned long long a,
                                                    unsigned long long b,
                                                    unsigned long long c) {
    unsigned long long d;
    asm("fma.rn.f32x2 %0, %1, %2, %3;" : "=l"(d) : "l"(a), "l"(b), "l"(c));
    return d;
}
__device__ __forceinline__ float2 unpk2(unsigned long long v) {
    float2 f;
    asm("mov.b64 {%0, %1}, %2;" : "=f"(f.x), "=f"(f.y) : "l"(v));
    return f;
}

// ---- GEMM tile: y[row0..row0+63] = x[row0..row0+63] @ W, stored as fp16.
// A staged TRANSPOSED in smem (As[k][r]) so each thread's 8 row-values for a
// given k are contiguous -> 2x LDS.128 yields row-PAIR-packed u64 operands for
// FFMA2 with no packing MOVs. As is __align__(16) so the 128-bit LDS is legal.
// W stays in its native 64 KB layout (L1-hot); the duplicated-w operand is
// built with pk2 MOVs in-loop (a 128 KB pre-dup W blows L1 and regresses, R13).
__device__ __forceinline__ void gemm_body(int blk, const float* __restrict__ x,
                                          const float* __restrict__ W) {
    __shared__ __align__(16) float As[D * TILE_R];   // As[k*64 + r], 32 KB
    int row0 = blk * TILE_R;
    int t = threadIdx.x;

    // stage x tile transposed: 64 rows x 32 float4-cols, 2048 float4s / 256 thr
    for (int i = t; i < TILE_R * (D / 4); i += 256) {
        int r  = i & (TILE_R - 1);
        int c4 = i >> 6;
        int row = row0 + r;
        float4 v = (row < N_NODES)
                       ? ((const float4*)(x + (size_t)row * D))[c4]
                       : make_float4(0.f, 0.f, 0.f, 0.f);
        As[(c4 * 4 + 0) * TILE_R + r] = v.x;
        As[(c4 * 4 + 1) * TILE_R + r] = v.y;
        As[(c4 * 4 + 2) * TILE_R + r] = v.z;
        As[(c4 * 4 + 3) * TILE_R + r] = v.w;
    }
    __syncthreads();

    int tc = t & 31;   // col group: cols 4*tc .. 4*tc+3
    int tr = t >> 5;   // row group: rows 8*tr .. 8*tr+7

    unsigned long long acc[4][4];              // [rowpair][col]
    #pragma unroll
    for (int rp = 0; rp < 4; rp++)
        #pragma unroll
        for (int c = 0; c < 4; c++) acc[rp][c] = 0ULL;

    const float* as_base = As + tr * 8;        // (k*64 + tr*8)*4B: 32B-multiple offsets

    #pragma unroll 4
    for (int k = 0; k < D; k++) {
        float4 w = ((const float4*)(W + (size_t)k * D))[tc];
        unsigned long long w2[4];
        w2[0] = pk2(w.x, w.x);
        w2[1] = pk2(w.y, w.y);
        w2[2] = pk2(w.z, w.z);
        w2[3] = pk2(w.w, w.w);
        ulonglong2 A0 = *(const ulonglong2*)(as_base + k * TILE_R);      // rows 0-3
        ulonglong2 A1 = *(const ulonglong2*)(as_base + k * TILE_R + 4);  // rows 4-7
        #pragma unroll
        for (int c = 0; c < 4; c++) {
            acc[0][c] = ffma2(A0.x, w2[c], acc[0][c]);
            acc[1][c] = ffma2(A0.y, w2[c], acc[1][c]);
            acc[2][c] = ffma2(A1.x, w2[c], acc[2][c]);
            acc[3][c] = ffma2(A1.y, w2[c], acc[3][c]);
        }
    }

    #pragma unroll
    for (int rp = 0; rp < 4; rp++) {
        float2 c0 = unpk2(acc[rp][0]);
        float2 c1 = unpk2(acc[rp][1]);
        float2 c2 = unpk2(acc[rp][2]);
        float2 c3 = unpk2(acc[rp][3]);
        int r_lo = row0 + tr * 8 + rp * 2;
        int r_hi = r_lo + 1;
        if (r_lo < N_NODES) {
            __half2 p0 = __floats2half2_rn(c0.x, c1.x);
            __half2 p1 = __floats2half2_rn(c2.x, c3.x);
            uint2 u;
            u.x = *(unsigned int*)&p0;
            u.y = *(unsigned int*)&p1;
            ((uint2*)(g_yh + (size_t)r_lo * D))[tc] = u;
        }
        if (r_hi < N_NODES) {
            __half2 p0 = __floats2half2_rn(c0.y, c1.y);
            __half2 p1 = __floats2half2_rn(c2.y, c3.y);
            uint2 u;
            u.x = *(unsigned int*)&p0;
            u.y = *(unsigned int*)&p1;
            ((uint2*)(g_yh + (size_t)r_hi * D))[tc] = u;
        }
    }
    __syncthreads();   // protect As before next tile
}

// Work-stealing GEMM loop: grab tiles from the global cursor until drained.
__device__ __forceinline__ void gemm_steal(const float* __restrict__ x,
                                           const float* __restrict__ W) {
    __shared__ int s_tile;
    for (;;) {
        __syncthreads();                       // protect s_tile reuse
        if (threadIdx.x == 0) s_tile = atomicAdd(&g_tile, 1);
        __syncthreads();
        int tile = s_tile;
        if (tile >= GEMM_TILES) break;
        gemm_body(tile, x, W);
    }
}

// ---- Launch 1: persistent kernel (zero + build + GEMM, work-conserving).
// Blocks [0,NC): zero -> count -> scan -> fill (group barriers 0..4), then JOIN
// the GEMM stealing loop. Blocks [NC,NB): GEMM stealing from the start.
// The kernel boundary is the global join before aggregation.
__global__ void __launch_bounds__(256, 3)
k_main(const float* __restrict__ x, const void* __restrict__ src,
       const void* __restrict__ dst, const float* __restrict__ W) {
    int blk = blockIdx.x;
    int t = threadIdx.x;

    if (blk < NC) {
        __shared__ int s_scan[256];
        __shared__ int s_ok;

        // int64/int32 detection, block-local. (JAX without x64 downcasts
        // int64->int32; the odd 32-bit words of src are all zero iff the data
        // is 8-byte little-endian values < 2^31.)
        if (t == 0) s_ok = 1;
        __syncthreads();
        if (t < 64 && ((const unsigned int*)src)[2 * t + 1] != 0u) s_ok = 0;
        // Phase C0: zero the degree array (interleaved with detection)
        for (int i = blk * 256 + t; i < N_NODES; i += NC * 256) g_deg[i] = 0;
        __syncthreads();
        int is64 = s_ok;
        barwait(0, NC);

        // Phase C1: degree histogram (unroll 2: MLP on the index loads)
        #pragma unroll 2
        for (int e = blk * 256 + t; e < N_EDGES; e += NC * 256) {
            int d = load_idx(dst, e, is64);
            atomicAdd(&g_deg[d], 1);
        }
        barwait(1, NC);

        // Phase C2: per-thread partial sums (contiguous CT nodes each)
        int base = (blk * 256 + t) * CT;
        int dcache[CT];
        int mysum = 0;
        #pragma unroll
        for (int i = 0; i < CT; i++) {
            int idx = base + i;
            dcache[i] = (idx < N_NODES) ? g_deg[idx] : 0;
            mysum += dcache[i];
        }
        s_scan[t] = mysum;
        __syncthreads();
        #pragma unroll
        for (int ofs = 1; ofs < 256; ofs <<= 1) {
            int v = (t >= ofs) ? s_scan[t - ofs] : 0;
            __syncthreads();
            s_scan[t] += v;
            __syncthreads();
        }
        int excl = s_scan[t] - mysum;
        if (t == 255) g_part[blk] = s_scan[255];
        barwait(2, NC);

        // Phase C3: warp-scan of the NC block partials (block 0, warp 0)
        if (blk == 0 && t < 32) {
            int carry = 0;
            #pragma unroll
            for (int seg = 0; seg < NC / 32; seg++) {
                int orig = g_part[seg * 32 + t];
                int v = orig;
                #pragma unroll
                for (int o = 1; o < 32; o <<= 1) {
                    int u = __shfl_up_sync(0xFFFFFFFFu, v, o);
                    if (t >= o) v += u;
                }
                g_pscan[seg * 32 + t] = carry + v - orig;   // exclusive
                carry += __shfl_sync(0xFFFFFFFFu, v, 31);
            }
        }
        barwait(3, NC);

        // Phase C4: write offsets, cursors, rsqrt(deg)
        int run = g_pscan[blk] + excl;
        #pragma unroll
        for (int i = 0; i < CT; i++) {
            int idx = base + i;
            if (idx < N_NODES) {
                g_off[idx] = run;
                g_cur[idx] = run;
                g_inv[idx] = rsqrtf((float)dcache[i]);
                run += dcache[i];
                if (idx == N_NODES - 1) g_off[N_NODES] = run;
            }
        }
        barwait(4, NC);

        // Phase C5: CSR fill via atomic cursors (unroll 2: MLP on index loads).
        // Fuse the source coefficient into the entry ({byte offset, inv[s]})
        // so the aggregate kernel does one contiguous LDG.64 instead of an
        // index load + dependent gather. The inv[s] gather cost lands HERE,
        // hidden under the concurrent GEMM.
        #pragma unroll 2
        for (int e = blk * 256 + t; e < N_EDGES; e += NC * 256) {
            int d = load_idx(dst, e, is64);
            int s = load_idx(src, e, is64);
            int pos = atomicAdd(&g_cur[d], 1);
            int2 ent;
            ent.x = s * (D * 2);               // byte offset into g_yh
            ent.y = __float_as_int(g_inv[s]);
            g_csr[pos] = ent;
        }
        // done building -> help finish the GEMM
        gemm_steal(x, W);
    } else {
        // ===== GEMM: y = x @ W (independent of the graph) =====
        gemm_steal(x, W);
    }
}

// ---- Launch 2: gather-aggregate + epilogue (fp16 y gather, fp32 accumulate).
// One warp per node; each lane owns 4 cols (8B load per neighbor row).
// Unroll-4 with narrow independent LDG.64 entry loads is the measured optimum
// of this design (unroll-8 drops occupancy, int4 pairing halves MLP; R14/R16).
// out[d] = inv[d] * sum_{s in N(d)} inv[s] * y[s]  +  deg[d] * b
// Also resets the barrier/tile counters for the next replay (stream-ordered
// after k_main, so no race with the polls).
__global__ void __launch_bounds__(256)
k_agg(const float* __restrict__ b, float* __restrict__ out) {
    if (blockIdx.x == 0) {
        if (threadIdx.x < 8) g_bar[threadIdx.x] = 0;
        if (threadIdx.x == 8) g_tile = 0;
    }

    int w    = (blockIdx.x * blockDim.x + threadIdx.x) >> 5;
    int lane = threadIdx.x & 31;
    if (w >= N_NODES) return;
    int beg = g_off[w];
    int end = g_off[w + 1];

    const char* ybase = (const char*)g_yh + lane * 8;   // lane's 8B column slice
    float4 acc = make_float4(0.f, 0.f, 0.f, 0.f);
    int e = beg;

    // unroll-4: batch entry loads, then 4 independent row loads (MLP>=4)
    for (; e + 4 <= end; e += 4) {
        int2 p0 = g_csr[e];
        int2 p1 = g_csr[e + 1];
        int2 p2 = g_csr[e + 2];
        int2 p3 = g_csr[e + 3];
        float c0 = __int_as_float(p0.y);
        float c1 = __int_as_float(p1.y);
        float c2 = __int_as_float(p2.y);
        float c3 = __int_as_float(p3.y);
        uint2 u0 = *(const uint2*)(ybase + p0.x);
        uint2 u1 = *(const uint2*)(ybase + p1.x);
        uint2 u2 = *(const uint2*)(ybase + p2.x);
        uint2 u3 = *(const uint2*)(ybase + p3.x);
        float2 a0 = __half22float2(*(__half2*)&u0.x), b0 = __half22float2(*(__half2*)&u0.y);
        float2 a1 = __half22float2(*(__half2*)&u1.x), b1 = __half22float2(*(__half2*)&u1.y);
        float2 a2 = __half22float2(*(__half2*)&u2.x), b2 = __half22float2(*(__half2*)&u2.y);
        float2 a3 = __half22float2(*(__half2*)&u3.x), b3 = __half22float2(*(__half2*)&u3.y);
        acc.x += c0 * a0.x + c1 * a1.x + c2 * a2.x + c3 * a3.x;
        acc.y += c0 * a0.y + c1 * a1.y + c2 * a2.y + c3 * a3.y;
        acc.z += c0 * b0.x + c1 * b1.x + c2 * b2.x + c3 * b3.x;
        acc.w += c0 * b0.y + c1 * b1.y + c2 * b2.y + c3 * b3.y;
    }
    for (; e < end; e++) {
        int2 p = g_csr[e];
        float c = __int_as_float(p.y);
        uint2 u = *(const uint2*)(ybase + p.x);
        float2 a = __half22float2(*(__half2*)&u.x);
        float2 bb = __half22float2(*(__half2*)&u.y);
        acc.x += c * a.x; acc.y += c * a.y; acc.z += c * bb.x; acc.w += c * bb.y;
    }

    float invd = g_inv[w];
    float degf = (float)g_deg[w];
    float4 bv = ((const float4*)b)[lane];
    float4 o;
    o.x = invd * acc.x + degf * bv.x;
    o.y = invd * acc.y + degf * bv.y;
    o.z = invd * acc.z + degf * bv.z;
    o.w = invd * acc.w + degf * bv.w;
    ((float4*)(out + (size_t)w * D))[lane] = o;
}

extern "C" void kernel_launch(void* const* d_in, const int* in_sizes, int n_in,
                              void* d_out, int out_size) {
    const float* x   = (const float*)d_in[0];
    const void*  src = d_in[1];
    const void*  dst = d_in[2];
    const float* W   = (const float*)d_in[3];
    const float* b   = (const float*)d_in[4];
    float* out = (float*)d_out;

    (void)in_sizes; (void)n_in; (void)out_size;

    k_main<<<NB, 256>>>(x, src, dst, W);
    k_agg<<<(N_NODES * 32 + 255) / 256, 256>>>(b, out);
}